// round 15
// baseline (speedup 1.0000x reference)
#include <cuda_runtime.h>
#include <cuda_bf16.h>
#include <cuda_fp16.h>
#include <math.h>
#include <stdint.h>

#define BATCH 1024
#define DIN   256
#define HID   512
#define KOUT  32
#define NOUT  (DIN * KOUT)  // 8192

// Scratch (allocation-free rule -> __device__ globals), all fp16
__device__ half g_xq[BATCH * DIN];
__device__ half g_w0q[HID * DIN];
__device__ half g_w1q[HID * HID];
__device__ half g_w2q[HID * HID];
__device__ half g_h0q[BATCH * HID];
__device__ half g_h1q[BATCH * HID];
__device__ half g_h2q[BATCH * HID];
__device__ half g_wq[NOUT * HID];

// ---------------------------------------------------------------------------
// PTX helpers
// ---------------------------------------------------------------------------
__device__ __forceinline__ uint32_t smem_u32(const void* p) {
    uint32_t a;
    asm("{ .reg .u64 t; cvta.to.shared.u64 t, %1; cvt.u32.u64 %0, t; }" : "=r"(a) : "l"(p));
    return a;
}
__device__ __forceinline__ void ldm_x4(uint32_t* r, uint32_t addr) {
    asm volatile("ldmatrix.sync.aligned.m8n8.x4.shared.b16 {%0,%1,%2,%3}, [%4];"
                 : "=r"(r[0]), "=r"(r[1]), "=r"(r[2]), "=r"(r[3]) : "r"(addr));
}
__device__ __forceinline__ void mma_f16(float* d, const uint32_t* a, const uint32_t* b) {
    asm volatile("mma.sync.aligned.m16n8k16.row.col.f32.f16.f16.f32 "
                 "{%0,%1,%2,%3}, {%4,%5,%6,%7}, {%8,%9}, {%0,%1,%2,%3};"
                 : "+f"(d[0]), "+f"(d[1]), "+f"(d[2]), "+f"(d[3])
                 : "r"(a[0]), "r"(a[1]), "r"(a[2]), "r"(a[3]), "r"(b[0]), "r"(b[1]));
}
__device__ __forceinline__ void cp16(uint32_t dst, const void* src) {
    asm volatile("cp.async.cg.shared.global [%0], [%1], 16;" :: "r"(dst), "l"(src) : "memory");
}
__device__ __forceinline__ void cp_commit() {
    asm volatile("cp.async.commit_group;" ::: "memory");
}
template<int N> __device__ __forceinline__ void cp_wait() {
    asm volatile("cp.async.wait_group %0;" :: "n"(N) : "memory");
}
// min of (k % 255) over k in [a, a+32)
__device__ __forceinline__ int minmod255(int a) {
    return ((a + 31) / 255 > a / 255) ? 0 : (a % 255);
}

// ---------------------------------------------------------------------------
// Prep: quantize x, W0, W1, W2 to fp16 with masks folded in.
// ---------------------------------------------------------------------------
__global__ void __launch_bounds__(256) prep_kernel(
    const float* __restrict__ x,  const float* __restrict__ W0,
    const float* __restrict__ W1, const float* __restrict__ W2)
{
    int t = blockIdx.x * 256 + threadIdx.x;
    const float* src; half* dst;
    int mode, ksh, base;
    if (t < 65536)       { src = x;  dst = g_xq;  mode = -1; ksh = 8; base = t * 4; }
    else if (t < 98304)  { src = W0; dst = g_w0q; mode = 0;  ksh = 8; base = (t - 65536) * 4; }
    else if (t < 163840) { src = W1; dst = g_w1q; mode = 1;  ksh = 9; base = (t - 98304) * 4; }
    else                 { src = W2; dst = g_w2q; mode = 1;  ksh = 9; base = (t - 163840) * 4; }

    float4 v4 = *(const float4*)(src + base);
    float vv[4] = {v4.x, v4.y, v4.z, v4.w};
    int n = base >> ksh;
    int k0 = base & ((1 << ksh) - 1);
    int nd = n % 255;
    half h[4];
    #pragma unroll
    for (int q = 0; q < 4; q++) {
        float v = vv[q];
        int k = k0 + q;
        if (mode == 0 && !(nd >= k)) v = 0.0f;
        if (mode == 1 && !(nd >= (k % 255))) v = 0.0f;
        h[q] = __float2half(v);
    }
    *(uint2*)(dst + base) = *(uint2*)h;
}

// Wout quantize with output mask (MODE 2) -> fp16
__global__ void __launch_bounds__(256) split_wout_kernel(const float* __restrict__ W)
{
    int idx = blockIdx.x * 256 + threadIdx.x;
    int base = idx * 4;
    int n = base >> 9, k0 = base & 511;
    int od = (n >> 5) - 1;
    float4 w4 = *(const float4*)(W + base);
    float wv[4] = {w4.x, w4.y, w4.z, w4.w};
    half h[4];
    #pragma unroll
    for (int q = 0; q < 4; q++) {
        float v = (od >= ((k0 + q) % 255)) ? wv[q] : 0.0f;
        h[q] = __float2half(v);
    }
    *(uint2*)(g_wq + base) = *(uint2*)h;
}

// ---------------------------------------------------------------------------
// Small-layer fp16 HMMA kernel (R14 champion, unchanged).
// ---------------------------------------------------------------------------
template<int K, int MODE>
__global__ void __launch_bounds__(128) layer_kernel(
    const half* __restrict__ Aq, const half* __restrict__ Wq,
    const float* __restrict__ bias, half* __restrict__ Cq)
{
    constexpr int NC = K / 32;
    constexpr int S = 3;
    constexpr uint32_t STG = 6144;
    extern __shared__ half smL[];
    const int tid = threadIdx.x, lane = tid & 31, wn = tid >> 5;
    const int bm = blockIdx.y * 32;
    const int bn = ((int)gridDim.x - 1 - (int)blockIdx.x) * 64;
    const uint32_t sb = smem_u32(smL);

    const int md = (bn / 255 == (bn + 63) / 255) ? ((bn + 63) % 255) : 254;

    int act[NC]; int na = 0;
    #pragma unroll
    for (int kc = 0; kc < NC; kc++) {
        int mm = (MODE == 0) ? (32 * kc) : minmod255(32 * kc);
        if (md >= mm) act[na++] = kc;
    }

    auto load_stage = [&](int s, int kc) {
        uint32_t stg = sb + (uint32_t)s * STG;
        {
            int r = tid >> 2, c = tid & 3;
            uint32_t dsw = (uint32_t)(r * 64 + ((c ^ ((r >> 1) & 3)) << 4));
            cp16(stg + dsw, Aq + (size_t)(bm + r) * K + kc * 32 + c * 8);
        }
        #pragma unroll
        for (int i = 0; i < 2; i++) {
            int idx = tid + i * 128;
            int r = idx >> 2, c = idx & 3;
            uint32_t dsw = (uint32_t)(r * 64 + ((c ^ ((r >> 1) & 3)) << 4));
            cp16(stg + 2048u + dsw, Wq + (size_t)(bn + r) * K + kc * 32 + c * 8);
        }
    };

    int raby[2], swa[2];
    #pragma unroll
    for (int mi = 0; mi < 2; mi++) {
        int r = mi * 16 + (lane & 15);
        raby[mi] = r * 64;
        swa[mi] = (r >> 1) & 3;
    }
    const int hiA = lane >> 4;
    const int nloc = wn * 16 + (((lane >> 3) >> 1) << 3) + (lane & 7);
    const int rbby = nloc * 64, swb = (nloc >> 1) & 3, cbB = (lane >> 3) & 1;

    float acc[2][2][4];
    #pragma unroll
    for (int a = 0; a < 2; a++)
        #pragma unroll
        for (int bq = 0; bq < 2; bq++)
            #pragma unroll
            for (int q = 0; q < 4; q++) acc[a][bq][q] = 0.0f;

    #pragma unroll
    for (int s = 0; s < S - 1; s++) { if (s < na) load_stage(s, act[s]); cp_commit(); }

    #pragma unroll 1
    for (int ii = 0; ii < na; ii++) {
        cp_wait<S - 2>();
        __syncthreads();
        int ld = ii + S - 1;
        if (ld < na) load_stage(ld % S, act[ld]);
        cp_commit();

        uint32_t stg = sb + (uint32_t)(ii % S) * STG;
        #pragma unroll
        for (int k16 = 0; k16 < 2; k16++) {
            uint32_t a0[2][4];
            #pragma unroll
            for (int mi = 0; mi < 2; mi++) {
                uint32_t off = (uint32_t)(raby[mi] + ((((k16 << 1) | hiA) ^ swa[mi]) << 4));
                ldm_x4(a0[mi], stg + off);
            }
            uint32_t boff = (uint32_t)(rbby + ((((k16 << 1) | cbB) ^ swb) << 4));
            uint32_t bh[4];
            ldm_x4(bh, stg + 2048u + boff);
            #pragma unroll
            for (int mi = 0; mi < 2; mi++) {
                mma_f16(acc[mi][0], a0[mi], &bh[0]);
                mma_f16(acc[mi][1], a0[mi], &bh[2]);
            }
        }
    }
    cp_wait<0>();

    const int r0 = bm + (lane >> 2);
    const int c0 = bn + wn * 16 + (lane & 3) * 2;
    #pragma unroll
    for (int mi = 0; mi < 2; mi++) {
        #pragma unroll
        for (int nj = 0; nj < 2; nj++) {
            int c = c0 + nj * 8;
            float b0 = bias[c], b1 = bias[c + 1];
            float v00 = fmaxf(acc[mi][nj][0] + b0, 0.0f);
            float v01 = fmaxf(acc[mi][nj][1] + b1, 0.0f);
            float v10 = fmaxf(acc[mi][nj][2] + b0, 0.0f);
            float v11 = fmaxf(acc[mi][nj][3] + b1, 0.0f);
            *(half2*)(Cq + (size_t)(r0 + mi * 16) * HID + c)     = __floats2half2_rn(v00, v01);
            *(half2*)(Cq + (size_t)(r0 + mi * 16 + 8) * HID + c) = __floats2half2_rn(v10, v11);
        }
    }
}

// ---------------------------------------------------------------------------
// Big fp16 HMMA GEMM (R14 champion, unchanged).
// ---------------------------------------------------------------------------
__global__ void __launch_bounds__(256) gemm_f16_kernel(
    const half* __restrict__ Af, const half* __restrict__ Wf,
    const float* __restrict__ bias, float* __restrict__ C)
{
    constexpr int NC = HID / 32;   // 16
    constexpr int S = 3;
    constexpr uint32_t STG = 16384;
    extern __shared__ half smd[];
    const int tid = threadIdx.x, lane = tid & 31, wrp = tid >> 5;
    const int wm = wrp >> 2, wn = wrp & 3;
    const int bm = blockIdx.y * 128;
    const int bn = ((int)gridDim.x - 1 - (int)blockIdx.x) * 128;
    const uint32_t sb = smem_u32(smd);

    const int T = (bn >> 5) + 2;
    int act[NC]; int na = 0;
    #pragma unroll
    for (int kc = 0; kc < NC; kc++)
        if (minmod255(32 * kc) <= T) act[na++] = kc;

    auto load_stage = [&](int s, int kc) {
        uint32_t stg = sb + (uint32_t)s * STG;
        #pragma unroll
        for (int i = 0; i < 2; i++) {
            int idx = tid + i * 256;
            int r = idx >> 2, c = idx & 3;
            uint32_t dsw = (uint32_t)(r * 64 + ((c ^ ((r >> 1) & 3)) << 4));
            cp16(stg + dsw,         Af + (size_t)(bm + r) * HID + kc * 32 + c * 8);
            cp16(stg + 8192u + dsw, Wf + (size_t)(bn + r) * HID + kc * 32 + c * 8);
        }
    };

    int raby[4], swa[4];
    #pragma unroll
    for (int mi = 0; mi < 4; mi++) {
        int r = wm * 64 + mi * 16 + (lane & 15);
        raby[mi] = r * 64;
        swa[mi] = (r >> 1) & 3;
    }
    const int hiA = lane >> 4;
    int rbby[2], swb[2];
    #pragma unroll
    for (int p = 0; p < 2; p++) {
        int n = wn * 32 + p * 16 + (((lane >> 3) >> 1) << 3) + (lane & 7);
        rbby[p] = n * 64;
        swb[p] = (n >> 1) & 3;
    }
    const int cbB = (lane >> 3) & 1;

    float acc[4][4][4];
    #pragma unroll
    for (int a = 0; a < 4; a++)
        #pragma unroll
        for (int bq = 0; bq < 4; bq++)
            #pragma unroll
            for (int q = 0; q < 4; q++) acc[a][bq][q] = 0.0f;

    #pragma unroll
    for (int s = 0; s < S - 1; s++) { if (s < na) load_stage(s, act[s]); cp_commit(); }

    #pragma unroll 1
    for (int ii = 0; ii < na; ii++) {
        cp_wait<S - 2>();
        __syncthreads();
        int ld = ii + S - 1;
        if (ld < na) load_stage(ld % S, act[ld]);
        cp_commit();

        uint32_t stg = sb + (uint32_t)(ii % S) * STG;
        #pragma unroll
        for (int k16 = 0; k16 < 2; k16++) {
            uint32_t a[4][4];
            #pragma unroll
            for (int mi = 0; mi < 4; mi++) {
                uint32_t off = (uint32_t)(raby[mi] + ((((k16 << 1) | hiA) ^ swa[mi]) << 4));
                ldm_x4(a[mi], stg + off);
            }
            #pragma unroll
            for (int p = 0; p < 2; p++) {
                uint32_t boff = (uint32_t)(rbby[p] + ((((k16 << 1) | cbB) ^ swb[p]) << 4));
                uint32_t wh[4];
                ldm_x4(wh, stg + 8192u + boff);
                #pragma unroll
                for (int mi = 0; mi < 4; mi++) {
                    mma_f16(acc[mi][p * 2 + 0], a[mi], &wh[0]);
                    mma_f16(acc[mi][p * 2 + 1], a[mi], &wh[2]);
                }
            }
        }
    }
    cp_wait<0>();

    const int r0 = bm + wm * 64 + (lane >> 2);
    const int cbase = bn + wn * 32 + (lane & 3) * 2;
    #pragma unroll
    for (int mi = 0; mi < 4; mi++) {
        #pragma unroll
        for (int nj = 0; nj < 4; nj++) {
            int col = cbase + nj * 8;
            float b0 = bias[col], b1 = bias[col + 1];
            float2 v0 = {acc[mi][nj][0] + b0, acc[mi][nj][1] + b1};
            float2 v1 = {acc[mi][nj][2] + b0, acc[mi][nj][3] + b1};
            *(float2*)(C + (size_t)(r0 + mi * 16) * NOUT + col)     = v0;
            *(float2*)(C + (size_t)(r0 + mi * 16 + 8) * NOUT + col) = v1;
        }
    }
}

// ---------------------------------------------------------------------------
// Fused log_px + forward chain. 16 lanes/batch, 2 batches/warp.
// CHANGE: max-free offset LSE — offset = own previous carry (valid for any
// offset; bounded args since states mix). Removes 2 max-shuffles (~60 cyc)
// from the serial dependency chain. d=255 keeps the maxed reduction.
// ---------------------------------------------------------------------------
__global__ void __launch_bounds__(128) chain_kernel(
    const float* __restrict__ x, const float* __restrict__ theta,
    const float* __restrict__ ulpa, float* __restrict__ out)
{
    __shared__ float s_lpa[255 * 4];
    for (int d = threadIdx.x; d < 255; d += 128) {
        float u0 = ulpa[d * 4 + 0], u1 = ulpa[d * 4 + 1];
        float u2 = ulpa[d * 4 + 2], u3 = ulpa[d * 4 + 3];
        float m = fmaxf(fmaxf(u0, u1), fmaxf(u2, u3));
        float s = expf(u0 - m) + expf(u1 - m) + expf(u2 - m) + expf(u3 - m);
        float lse = m + logf(s);
        s_lpa[d * 4 + 0] = u0 - lse;
        s_lpa[d * 4 + 1] = u1 - lse;
        s_lpa[d * 4 + 2] = u2 - lse;
        s_lpa[d * 4 + 3] = u3 - lse;
    }
    __syncthreads();

    const int lane = threadIdx.x & 31;
    const int wid  = threadIdx.x >> 5;
    const int half_ = lane >> 4;
    const int l    = lane & 15;
    const int i    = l >> 2, j = l & 3;
    const int b    = (blockIdx.x * 4 + wid) * 2 + half_;

    const unsigned FULL = 0xffffffffu;
    const float NL = -0.91893853320467274178f;

    const float* th = theta + (size_t)b * NOUT;
    const float* xb = x + (size_t)b * DIN;

    float carry;
    {
        float mu = __ldg(th + l), ls = __ldg(th + 16 + l);
        float xd = __ldg(xb);
        float sd = __expf(ls) + 0.01f;
        float z = __fdividef(xd - mu, sd);
        float lp = fmaf(-0.5f * z, z, NL) - __logf(sd);
        float v = lp + s_lpa[j];
        carry = __shfl_sync(FULL, v, half_ * 16 + j);
    }
    float mu = __ldg(th + 32 + l), ls = __ldg(th + 48 + l);
    float xd = __ldg(xb + 1);
    #pragma unroll 1
    for (int d = 1; d < 255; d++) {
        float nmu = __ldg(th + (d + 1) * 32 + l);
        float nls = __ldg(th + (d + 1) * 32 + 16 + l);
        float nxd = __ldg(xb + d + 1);
        float sd = __expf(ls) + 0.01f;
        float z = __fdividef(xd - mu, sd);
        float lp = fmaf(-0.5f * z, z, NL) - __logf(sd);
        float bterm = lp + s_lpa[d * 4 + j];       // off critical path
        float ci = __shfl_sync(FULL, carry, half_ * 16 + i);
        float e = __expf(ci + bterm - carry);      // offset = own carry_j
        float s = e + __shfl_xor_sync(FULL, e, 4);
        s += __shfl_xor_sync(FULL, s, 8);
        carry += __logf(s + 1e-30f);
        mu = nmu; ls = nls; xd = nxd;
    }
    {
        float sd = __expf(ls) + 0.01f;
        float z = __fdividef(xd - mu, sd);
        float lp = fmaf(-0.5f * z, z, NL) - __logf(sd);
        float ci = __shfl_sync(FULL, carry, half_ * 16 + i);
        float tv = (j == 0) ? (ci + lp) : -1e30f;
        float m = fmaxf(tv, __shfl_xor_sync(FULL, tv, 1));
        m = fmaxf(m, __shfl_xor_sync(FULL, m, 2));
        m = fmaxf(m, __shfl_xor_sync(FULL, m, 4));
        m = fmaxf(m, __shfl_xor_sync(FULL, m, 8));
        float s = __expf(tv - m);
        s += __shfl_xor_sync(FULL, s, 1);
        s += __shfl_xor_sync(FULL, s, 2);
        s += __shfl_xor_sync(FULL, s, 4);
        s += __shfl_xor_sync(FULL, s, 8);
        if (l == 0) out[b] = m + __logf(s);
    }
}

// ---------------------------------------------------------------------------
// kernel_launch (serial champion schedule; only chain inner loop changed)
// ---------------------------------------------------------------------------
extern "C" void kernel_launch(void* const* d_in, const int* in_sizes, int n_in,
                              void* d_out, int out_size)
{
    const float* x    = (const float*)d_in[0];
    const float* W0   = (const float*)d_in[1];
    const float* b0   = (const float*)d_in[2];
    const float* W1   = (const float*)d_in[3];
    const float* b1   = (const float*)d_in[4];
    const float* W2   = (const float*)d_in[5];
    const float* b2   = (const float*)d_in[6];
    const float* Wout = (const float*)d_in[7];
    const float* bout = (const float*)d_in[8];
    const float* ulpa = (const float*)d_in[9];

    float* out   = (float*)d_out;
    float* theta = out + BATCH;

    half *xq, *w0q, *w1q, *w2q, *h0q, *h1q, *h2q, *wq;
    cudaGetSymbolAddress((void**)&xq, g_xq);
    cudaGetSymbolAddress((void**)&w0q, g_w0q);
    cudaGetSymbolAddress((void**)&w1q, g_w1q);
    cudaGetSymbolAddress((void**)&w2q, g_w2q);
    cudaGetSymbolAddress((void**)&h0q, g_h0q);
    cudaGetSymbolAddress((void**)&h1q, g_h1q);
    cudaGetSymbolAddress((void**)&h2q, g_h2q);
    cudaGetSymbolAddress((void**)&wq, g_wq);

    cudaFuncSetAttribute(gemm_f16_kernel,
                         cudaFuncAttributeMaxDynamicSharedMemorySize, 49152);
    cudaFuncSetAttribute(layer_kernel<DIN, 0>,
                         cudaFuncAttributeMaxDynamicSharedMemorySize, 18432);
    cudaFuncSetAttribute(layer_kernel<HID, 1>,
                         cudaFuncAttributeMaxDynamicSharedMemorySize, 18432);

    split_wout_kernel<<<NOUT * HID / 4 / 256, 256>>>(Wout);
    prep_kernel<<<896, 256>>>(x, W0, W1, W2);

    layer_kernel<DIN, 0><<<dim3(HID / 64, BATCH / 32), 128, 18432>>>(
        xq, w0q, b0, h0q);
    layer_kernel<HID, 1><<<dim3(HID / 64, BATCH / 32), 128, 18432>>>(
        h0q, w1q, b1, h1q);
    layer_kernel<HID, 1><<<dim3(HID / 64, BATCH / 32), 128, 18432>>>(
        h1q, w2q, b2, h2q);

    gemm_f16_kernel<<<dim3(NOUT / 128, BATCH / 128), 256, 49152>>>(
        h2q, wq, bout, theta);

    chain_kernel<<<BATCH / 8, 128>>>(x, theta, ulpa, out);
}

// round 16
// speedup vs baseline: 1.4226x; 1.4226x over previous
#include <cuda_runtime.h>
#include <cuda_bf16.h>
#include <cuda_fp16.h>
#include <math.h>
#include <stdint.h>

#define BATCH 1024
#define DIN   256
#define HID   512
#define KOUT  32
#define NOUT  (DIN * KOUT)  // 8192

// Scratch (allocation-free rule -> __device__ globals), all fp16
__device__ half g_xq[BATCH * DIN];
__device__ half g_w0q[HID * DIN];
__device__ half g_w1q[HID * HID];
__device__ half g_w2q[HID * HID];
__device__ half g_h0q[BATCH * HID];
__device__ half g_h1q[BATCH * HID];
__device__ half g_h2q[BATCH * HID];
__device__ half g_wq[NOUT * HID];

// ---------------------------------------------------------------------------
// PTX helpers
// ---------------------------------------------------------------------------
__device__ __forceinline__ uint32_t smem_u32(const void* p) {
    uint32_t a;
    asm("{ .reg .u64 t; cvta.to.shared.u64 t, %1; cvt.u32.u64 %0, t; }" : "=r"(a) : "l"(p));
    return a;
}
__device__ __forceinline__ void ldm_x4(uint32_t* r, uint32_t addr) {
    asm volatile("ldmatrix.sync.aligned.m8n8.x4.shared.b16 {%0,%1,%2,%3}, [%4];"
                 : "=r"(r[0]), "=r"(r[1]), "=r"(r[2]), "=r"(r[3]) : "r"(addr));
}
__device__ __forceinline__ void mma_f16(float* d, const uint32_t* a, const uint32_t* b) {
    asm volatile("mma.sync.aligned.m16n8k16.row.col.f32.f16.f16.f32 "
                 "{%0,%1,%2,%3}, {%4,%5,%6,%7}, {%8,%9}, {%0,%1,%2,%3};"
                 : "+f"(d[0]), "+f"(d[1]), "+f"(d[2]), "+f"(d[3])
                 : "r"(a[0]), "r"(a[1]), "r"(a[2]), "r"(a[3]), "r"(b[0]), "r"(b[1]));
}
__device__ __forceinline__ void cp16(uint32_t dst, const void* src) {
    asm volatile("cp.async.cg.shared.global [%0], [%1], 16;" :: "r"(dst), "l"(src) : "memory");
}
__device__ __forceinline__ void cp_commit() {
    asm volatile("cp.async.commit_group;" ::: "memory");
}
template<int N> __device__ __forceinline__ void cp_wait() {
    asm volatile("cp.async.wait_group %0;" :: "n"(N) : "memory");
}
// min of (k % 255) over k in [a, a+32)
__device__ __forceinline__ int minmod255(int a) {
    return ((a + 31) / 255 > a / 255) ? 0 : (a % 255);
}

// ---------------------------------------------------------------------------
// Prep: quantize x, W0, W1, W2 to fp16 with masks folded in.
// ---------------------------------------------------------------------------
__global__ void __launch_bounds__(256) prep_kernel(
    const float* __restrict__ x,  const float* __restrict__ W0,
    const float* __restrict__ W1, const float* __restrict__ W2)
{
    int t = blockIdx.x * 256 + threadIdx.x;
    const float* src; half* dst;
    int mode, ksh, base;
    if (t < 65536)       { src = x;  dst = g_xq;  mode = -1; ksh = 8; base = t * 4; }
    else if (t < 98304)  { src = W0; dst = g_w0q; mode = 0;  ksh = 8; base = (t - 65536) * 4; }
    else if (t < 163840) { src = W1; dst = g_w1q; mode = 1;  ksh = 9; base = (t - 98304) * 4; }
    else                 { src = W2; dst = g_w2q; mode = 1;  ksh = 9; base = (t - 163840) * 4; }

    float4 v4 = *(const float4*)(src + base);
    float vv[4] = {v4.x, v4.y, v4.z, v4.w};
    int n = base >> ksh;
    int k0 = base & ((1 << ksh) - 1);
    int nd = n % 255;
    half h[4];
    #pragma unroll
    for (int q = 0; q < 4; q++) {
        float v = vv[q];
        int k = k0 + q;
        if (mode == 0 && !(nd >= k)) v = 0.0f;
        if (mode == 1 && !(nd >= (k % 255))) v = 0.0f;
        h[q] = __float2half(v);
    }
    *(uint2*)(dst + base) = *(uint2*)h;
}

// Wout quantize with output mask (MODE 2) -> fp16
__global__ void __launch_bounds__(256) split_wout_kernel(const float* __restrict__ W)
{
    int idx = blockIdx.x * 256 + threadIdx.x;
    int base = idx * 4;
    int n = base >> 9, k0 = base & 511;
    int od = (n >> 5) - 1;
    float4 w4 = *(const float4*)(W + base);
    float wv[4] = {w4.x, w4.y, w4.z, w4.w};
    half h[4];
    #pragma unroll
    for (int q = 0; q < 4; q++) {
        float v = (od >= ((k0 + q) % 255)) ? wv[q] : 0.0f;
        h[q] = __float2half(v);
    }
    *(uint2*)(g_wq + base) = *(uint2*)h;
}

// ---------------------------------------------------------------------------
// Small-layer fp16 HMMA kernel (R14 champion, unchanged).
// ---------------------------------------------------------------------------
template<int K, int MODE>
__global__ void __launch_bounds__(128) layer_kernel(
    const half* __restrict__ Aq, const half* __restrict__ Wq,
    const float* __restrict__ bias, half* __restrict__ Cq)
{
    constexpr int NC = K / 32;
    constexpr int S = 3;
    constexpr uint32_t STG = 6144;
    extern __shared__ half smL[];
    const int tid = threadIdx.x, lane = tid & 31, wn = tid >> 5;
    const int bm = blockIdx.y * 32;
    const int bn = ((int)gridDim.x - 1 - (int)blockIdx.x) * 64;
    const uint32_t sb = smem_u32(smL);

    const int md = (bn / 255 == (bn + 63) / 255) ? ((bn + 63) % 255) : 254;

    int act[NC]; int na = 0;
    #pragma unroll
    for (int kc = 0; kc < NC; kc++) {
        int mm = (MODE == 0) ? (32 * kc) : minmod255(32 * kc);
        if (md >= mm) act[na++] = kc;
    }

    auto load_stage = [&](int s, int kc) {
        uint32_t stg = sb + (uint32_t)s * STG;
        {
            int r = tid >> 2, c = tid & 3;
            uint32_t dsw = (uint32_t)(r * 64 + ((c ^ ((r >> 1) & 3)) << 4));
            cp16(stg + dsw, Aq + (size_t)(bm + r) * K + kc * 32 + c * 8);
        }
        #pragma unroll
        for (int i = 0; i < 2; i++) {
            int idx = tid + i * 128;
            int r = idx >> 2, c = idx & 3;
            uint32_t dsw = (uint32_t)(r * 64 + ((c ^ ((r >> 1) & 3)) << 4));
            cp16(stg + 2048u + dsw, Wq + (size_t)(bn + r) * K + kc * 32 + c * 8);
        }
    };

    int raby[2], swa[2];
    #pragma unroll
    for (int mi = 0; mi < 2; mi++) {
        int r = mi * 16 + (lane & 15);
        raby[mi] = r * 64;
        swa[mi] = (r >> 1) & 3;
    }
    const int hiA = lane >> 4;
    const int nloc = wn * 16 + (((lane >> 3) >> 1) << 3) + (lane & 7);
    const int rbby = nloc * 64, swb = (nloc >> 1) & 3, cbB = (lane >> 3) & 1;

    float acc[2][2][4];
    #pragma unroll
    for (int a = 0; a < 2; a++)
        #pragma unroll
        for (int bq = 0; bq < 2; bq++)
            #pragma unroll
            for (int q = 0; q < 4; q++) acc[a][bq][q] = 0.0f;

    #pragma unroll
    for (int s = 0; s < S - 1; s++) { if (s < na) load_stage(s, act[s]); cp_commit(); }

    #pragma unroll 1
    for (int ii = 0; ii < na; ii++) {
        cp_wait<S - 2>();
        __syncthreads();
        int ld = ii + S - 1;
        if (ld < na) load_stage(ld % S, act[ld]);
        cp_commit();

        uint32_t stg = sb + (uint32_t)(ii % S) * STG;
        #pragma unroll
        for (int k16 = 0; k16 < 2; k16++) {
            uint32_t a0[2][4];
            #pragma unroll
            for (int mi = 0; mi < 2; mi++) {
                uint32_t off = (uint32_t)(raby[mi] + ((((k16 << 1) | hiA) ^ swa[mi]) << 4));
                ldm_x4(a0[mi], stg + off);
            }
            uint32_t boff = (uint32_t)(rbby + ((((k16 << 1) | cbB) ^ swb) << 4));
            uint32_t bh[4];
            ldm_x4(bh, stg + 2048u + boff);
            #pragma unroll
            for (int mi = 0; mi < 2; mi++) {
                mma_f16(acc[mi][0], a0[mi], &bh[0]);
                mma_f16(acc[mi][1], a0[mi], &bh[2]);
            }
        }
    }
    cp_wait<0>();

    const int r0 = bm + (lane >> 2);
    const int c0 = bn + wn * 16 + (lane & 3) * 2;
    #pragma unroll
    for (int mi = 0; mi < 2; mi++) {
        #pragma unroll
        for (int nj = 0; nj < 2; nj++) {
            int c = c0 + nj * 8;
            float b0 = bias[c], b1 = bias[c + 1];
            float v00 = fmaxf(acc[mi][nj][0] + b0, 0.0f);
            float v01 = fmaxf(acc[mi][nj][1] + b1, 0.0f);
            float v10 = fmaxf(acc[mi][nj][2] + b0, 0.0f);
            float v11 = fmaxf(acc[mi][nj][3] + b1, 0.0f);
            *(half2*)(Cq + (size_t)(r0 + mi * 16) * HID + c)     = __floats2half2_rn(v00, v01);
            *(half2*)(Cq + (size_t)(r0 + mi * 16 + 8) * HID + c) = __floats2half2_rn(v10, v11);
        }
    }
}

// ---------------------------------------------------------------------------
// Big fp16 HMMA GEMM (R14 champion, unchanged).
// ---------------------------------------------------------------------------
__global__ void __launch_bounds__(256) gemm_f16_kernel(
    const half* __restrict__ Af, const half* __restrict__ Wf,
    const float* __restrict__ bias, float* __restrict__ C)
{
    constexpr int NC = HID / 32;   // 16
    constexpr int S = 3;
    constexpr uint32_t STG = 16384;
    extern __shared__ half smd[];
    const int tid = threadIdx.x, lane = tid & 31, wrp = tid >> 5;
    const int wm = wrp >> 2, wn = wrp & 3;
    const int bm = blockIdx.y * 128;
    const int bn = ((int)gridDim.x - 1 - (int)blockIdx.x) * 128;
    const uint32_t sb = smem_u32(smd);

    const int T = (bn >> 5) + 2;
    int act[NC]; int na = 0;
    #pragma unroll
    for (int kc = 0; kc < NC; kc++)
        if (minmod255(32 * kc) <= T) act[na++] = kc;

    auto load_stage = [&](int s, int kc) {
        uint32_t stg = sb + (uint32_t)s * STG;
        #pragma unroll
        for (int i = 0; i < 2; i++) {
            int idx = tid + i * 256;
            int r = idx >> 2, c = idx & 3;
            uint32_t dsw = (uint32_t)(r * 64 + ((c ^ ((r >> 1) & 3)) << 4));
            cp16(stg + dsw,         Af + (size_t)(bm + r) * HID + kc * 32 + c * 8);
            cp16(stg + 8192u + dsw, Wf + (size_t)(bn + r) * HID + kc * 32 + c * 8);
        }
    };

    int raby[4], swa[4];
    #pragma unroll
    for (int mi = 0; mi < 4; mi++) {
        int r = wm * 64 + mi * 16 + (lane & 15);
        raby[mi] = r * 64;
        swa[mi] = (r >> 1) & 3;
    }
    const int hiA = lane >> 4;
    int rbby[2], swb[2];
    #pragma unroll
    for (int p = 0; p < 2; p++) {
        int n = wn * 32 + p * 16 + (((lane >> 3) >> 1) << 3) + (lane & 7);
        rbby[p] = n * 64;
        swb[p] = (n >> 1) & 3;
    }
    const int cbB = (lane >> 3) & 1;

    float acc[4][4][4];
    #pragma unroll
    for (int a = 0; a < 4; a++)
        #pragma unroll
        for (int bq = 0; bq < 4; bq++)
            #pragma unroll
            for (int q = 0; q < 4; q++) acc[a][bq][q] = 0.0f;

    #pragma unroll
    for (int s = 0; s < S - 1; s++) { if (s < na) load_stage(s, act[s]); cp_commit(); }

    #pragma unroll 1
    for (int ii = 0; ii < na; ii++) {
        cp_wait<S - 2>();
        __syncthreads();
        int ld = ii + S - 1;
        if (ld < na) load_stage(ld % S, act[ld]);
        cp_commit();

        uint32_t stg = sb + (uint32_t)(ii % S) * STG;
        #pragma unroll
        for (int k16 = 0; k16 < 2; k16++) {
            uint32_t a[4][4];
            #pragma unroll
            for (int mi = 0; mi < 4; mi++) {
                uint32_t off = (uint32_t)(raby[mi] + ((((k16 << 1) | hiA) ^ swa[mi]) << 4));
                ldm_x4(a[mi], stg + off);
            }
            #pragma unroll
            for (int p = 0; p < 2; p++) {
                uint32_t boff = (uint32_t)(rbby[p] + ((((k16 << 1) | cbB) ^ swb[p]) << 4));
                uint32_t wh[4];
                ldm_x4(wh, stg + 8192u + boff);
                #pragma unroll
                for (int mi = 0; mi < 4; mi++) {
                    mma_f16(acc[mi][p * 2 + 0], a[mi], &wh[0]);
                    mma_f16(acc[mi][p * 2 + 1], a[mi], &wh[2]);
                }
            }
        }
    }
    cp_wait<0>();

    const int r0 = bm + wm * 64 + (lane >> 2);
    const int cbase = bn + wn * 32 + (lane & 3) * 2;
    #pragma unroll
    for (int mi = 0; mi < 4; mi++) {
        #pragma unroll
        for (int nj = 0; nj < 4; nj++) {
            int col = cbase + nj * 8;
            float b0 = bias[col], b1 = bias[col + 1];
            float2 v0 = {acc[mi][nj][0] + b0, acc[mi][nj][1] + b1};
            float2 v1 = {acc[mi][nj][2] + b0, acc[mi][nj][3] + b1};
            *(float2*)(C + (size_t)(r0 + mi * 16) * NOUT + col)     = v0;
            *(float2*)(C + (size_t)(r0 + mi * 16 + 8) * NOUT + col) = v1;
        }
    }
}

// ---------------------------------------------------------------------------
// Fused log_px + forward chain. 16 lanes/batch, 2 batches/warp.
// CHANGE vs R14: 4-deep register prefetch ring for theta/x — the serial
// scan was bound by L2 load latency (one-iter lookahead < 260cyc L2 hit);
// MLP 1 -> 4 hides it. Math identical to R14 (max-based LSE).
// ---------------------------------------------------------------------------
__global__ void __launch_bounds__(128) chain_kernel(
    const float* __restrict__ x, const float* __restrict__ theta,
    const float* __restrict__ ulpa, float* __restrict__ out)
{
    __shared__ float s_lpa[255 * 4];
    for (int d = threadIdx.x; d < 255; d += 128) {
        float u0 = ulpa[d * 4 + 0], u1 = ulpa[d * 4 + 1];
        float u2 = ulpa[d * 4 + 2], u3 = ulpa[d * 4 + 3];
        float m = fmaxf(fmaxf(u0, u1), fmaxf(u2, u3));
        float s = expf(u0 - m) + expf(u1 - m) + expf(u2 - m) + expf(u3 - m);
        float lse = m + logf(s);
        s_lpa[d * 4 + 0] = u0 - lse;
        s_lpa[d * 4 + 1] = u1 - lse;
        s_lpa[d * 4 + 2] = u2 - lse;
        s_lpa[d * 4 + 3] = u3 - lse;
    }
    __syncthreads();

    const int lane = threadIdx.x & 31;
    const int wid  = threadIdx.x >> 5;
    const int half_ = lane >> 4;
    const int l    = lane & 15;
    const int i    = l >> 2, j = l & 3;
    const int b    = (blockIdx.x * 4 + wid) * 2 + half_;

    const unsigned FULL = 0xffffffffu;
    const float NL = -0.91893853320467274178f;

    const float* th = theta + (size_t)b * NOUT;
    const float* xb = x + (size_t)b * DIN;

    float carry;
    {   // d = 0
        float mu = __ldg(th + l), ls = __ldg(th + 16 + l);
        float xd = __ldg(xb);
        float sd = __expf(ls) + 0.01f;
        float z = __fdividef(xd - mu, sd);
        float lp = fmaf(-0.5f * z, z, NL) - __logf(sd);
        float v = lp + s_lpa[j];
        carry = __shfl_sync(FULL, v, half_ * 16 + j);
    }

    // 4-slot register prefetch ring: slot q holds values for current d in
    // its group position; loads for d+4 issue before the compute of d.
    float mu0 = __ldg(th + 1 * 32 + l), ls0 = __ldg(th + 1 * 32 + 16 + l), xd0 = __ldg(xb + 1);
    float mu1 = __ldg(th + 2 * 32 + l), ls1 = __ldg(th + 2 * 32 + 16 + l), xd1 = __ldg(xb + 2);
    float mu2 = __ldg(th + 3 * 32 + l), ls2 = __ldg(th + 3 * 32 + 16 + l), xd2 = __ldg(xb + 3);
    float mu3 = __ldg(th + 4 * 32 + l), ls3 = __ldg(th + 4 * 32 + 16 + l), xd3 = __ldg(xb + 4);

#define CSTEP(DD, MU, LS, XD) do {                                          \
    int nd_ = (DD) + 4;                                                     \
    float pmu_ = 0.0f, pls_ = 0.0f, pxd_ = 0.0f;                            \
    if (nd_ < 256) {                                                        \
        pmu_ = __ldg(th + nd_ * 32 + l);                                    \
        pls_ = __ldg(th + nd_ * 32 + 16 + l);                               \
        pxd_ = __ldg(xb + nd_);                                             \
    }                                                                       \
    float sd_ = __expf(LS) + 0.01f;                                         \
    float z_ = __fdividef(XD - MU, sd_);                                    \
    float lp_ = fmaf(-0.5f * z_, z_, NL) - __logf(sd_);                     \
    float ci_ = __shfl_sync(FULL, carry, half_ * 16 + i);                   \
    float tv_ = ci_ + lp_ + s_lpa[(DD) * 4 + j];                            \
    float m_ = fmaxf(tv_, __shfl_xor_sync(FULL, tv_, 4));                   \
    m_ = fmaxf(m_, __shfl_xor_sync(FULL, m_, 8));                           \
    float s_ = __expf(tv_ - m_);                                            \
    s_ += __shfl_xor_sync(FULL, s_, 4);                                     \
    s_ += __shfl_xor_sync(FULL, s_, 8);                                     \
    carry = m_ + __logf(s_);                                                \
    MU = pmu_; LS = pls_; XD = pxd_;                                        \
} while (0)

    #pragma unroll 1
    for (int d = 1; d <= 249; d += 4) {
        CSTEP(d,     mu0, ls0, xd0);
        CSTEP(d + 1, mu1, ls1, xd1);
        CSTEP(d + 2, mu2, ls2, xd2);
        CSTEP(d + 3, mu3, ls3, xd3);
    }
    CSTEP(253, mu0, ls0, xd0);
    CSTEP(254, mu1, ls1, xd1);
#undef CSTEP

    {   // d = 255 (values live in slot 2)
        float sd = __expf(ls2) + 0.01f;
        float z = __fdividef(xd2 - mu2, sd);
        float lp = fmaf(-0.5f * z, z, NL) - __logf(sd);
        float ci = __shfl_sync(FULL, carry, half_ * 16 + i);
        float tv = (j == 0) ? (ci + lp) : -1e30f;
        float m = fmaxf(tv, __shfl_xor_sync(FULL, tv, 1));
        m = fmaxf(m, __shfl_xor_sync(FULL, m, 2));
        m = fmaxf(m, __shfl_xor_sync(FULL, m, 4));
        m = fmaxf(m, __shfl_xor_sync(FULL, m, 8));
        float s = __expf(tv - m);
        s += __shfl_xor_sync(FULL, s, 1);
        s += __shfl_xor_sync(FULL, s, 2);
        s += __shfl_xor_sync(FULL, s, 4);
        s += __shfl_xor_sync(FULL, s, 8);
        if (l == 0) out[b] = m + __logf(s);
    }
}

// ---------------------------------------------------------------------------
// kernel_launch (serial champion schedule; only chain prefetch changed)
// ---------------------------------------------------------------------------
extern "C" void kernel_launch(void* const* d_in, const int* in_sizes, int n_in,
                              void* d_out, int out_size)
{
    const float* x    = (const float*)d_in[0];
    const float* W0   = (const float*)d_in[1];
    const float* b0   = (const float*)d_in[2];
    const float* W1   = (const float*)d_in[3];
    const float* b1   = (const float*)d_in[4];
    const float* W2   = (const float*)d_in[5];
    const float* b2   = (const float*)d_in[6];
    const float* Wout = (const float*)d_in[7];
    const float* bout = (const float*)d_in[8];
    const float* ulpa = (const float*)d_in[9];

    float* out   = (float*)d_out;
    float* theta = out + BATCH;

    half *xq, *w0q, *w1q, *w2q, *h0q, *h1q, *h2q, *wq;
    cudaGetSymbolAddress((void**)&xq, g_xq);
    cudaGetSymbolAddress((void**)&w0q, g_w0q);
    cudaGetSymbolAddress((void**)&w1q, g_w1q);
    cudaGetSymbolAddress((void**)&w2q, g_w2q);
    cudaGetSymbolAddress((void**)&h0q, g_h0q);
    cudaGetSymbolAddress((void**)&h1q, g_h1q);
    cudaGetSymbolAddress((void**)&h2q, g_h2q);
    cudaGetSymbolAddress((void**)&wq, g_wq);

    cudaFuncSetAttribute(gemm_f16_kernel,
                         cudaFuncAttributeMaxDynamicSharedMemorySize, 49152);
    cudaFuncSetAttribute(layer_kernel<DIN, 0>,
                         cudaFuncAttributeMaxDynamicSharedMemorySize, 18432);
    cudaFuncSetAttribute(layer_kernel<HID, 1>,
                         cudaFuncAttributeMaxDynamicSharedMemorySize, 18432);

    split_wout_kernel<<<NOUT * HID / 4 / 256, 256>>>(Wout);
    prep_kernel<<<896, 256>>>(x, W0, W1, W2);

    layer_kernel<DIN, 0><<<dim3(HID / 64, BATCH / 32), 128, 18432>>>(
        xq, w0q, b0, h0q);
    layer_kernel<HID, 1><<<dim3(HID / 64, BATCH / 32), 128, 18432>>>(
        h0q, w1q, b1, h1q);
    layer_kernel<HID, 1><<<dim3(HID / 64, BATCH / 32), 128, 18432>>>(
        h1q, w2q, b2, h2q);

    gemm_f16_kernel<<<dim3(NOUT / 128, BATCH / 128), 256, 49152>>>(
        h2q, wq, bout, theta);

    chain_kernel<<<BATCH / 8, 128>>>(x, theta, ulpa, out);
}

// round 17
// speedup vs baseline: 1.5489x; 1.0888x over previous
#include <cuda_runtime.h>
#include <cuda_bf16.h>
#include <cuda_fp16.h>
#include <math.h>
#include <stdint.h>

#define BATCH 1024
#define DIN   256
#define HID   512
#define KOUT  32
#define NOUT  (DIN * KOUT)  // 8192

// Scratch (allocation-free rule -> __device__ globals), all fp16
__device__ half g_xq[BATCH * DIN];
__device__ half g_w0q[HID * DIN];
__device__ half g_w1q[HID * HID];
__device__ half g_w2q[HID * HID];
__device__ half g_h0q[BATCH * HID];
__device__ half g_h1q[BATCH * HID];
__device__ half g_h2q[BATCH * HID];
__device__ half g_wq[NOUT * HID];

// ---------------------------------------------------------------------------
// PTX helpers
// ---------------------------------------------------------------------------
__device__ __forceinline__ uint32_t smem_u32(const void* p) {
    uint32_t a;
    asm("{ .reg .u64 t; cvta.to.shared.u64 t, %1; cvt.u32.u64 %0, t; }" : "=r"(a) : "l"(p));
    return a;
}
__device__ __forceinline__ void ldm_x4(uint32_t* r, uint32_t addr) {
    asm volatile("ldmatrix.sync.aligned.m8n8.x4.shared.b16 {%0,%1,%2,%3}, [%4];"
                 : "=r"(r[0]), "=r"(r[1]), "=r"(r[2]), "=r"(r[3]) : "r"(addr));
}
__device__ __forceinline__ void mma_f16(float* d, const uint32_t* a, const uint32_t* b) {
    asm volatile("mma.sync.aligned.m16n8k16.row.col.f32.f16.f16.f32 "
                 "{%0,%1,%2,%3}, {%4,%5,%6,%7}, {%8,%9}, {%0,%1,%2,%3};"
                 : "+f"(d[0]), "+f"(d[1]), "+f"(d[2]), "+f"(d[3])
                 : "r"(a[0]), "r"(a[1]), "r"(a[2]), "r"(a[3]), "r"(b[0]), "r"(b[1]));
}
__device__ __forceinline__ void cp16(uint32_t dst, const void* src) {
    asm volatile("cp.async.cg.shared.global [%0], [%1], 16;" :: "r"(dst), "l"(src) : "memory");
}
__device__ __forceinline__ void cp_commit() {
    asm volatile("cp.async.commit_group;" ::: "memory");
}
template<int N> __device__ __forceinline__ void cp_wait() {
    asm volatile("cp.async.wait_group %0;" :: "n"(N) : "memory");
}
// min of (k % 255) over k in [a, a+32)
__device__ __forceinline__ int minmod255(int a) {
    return ((a + 31) / 255 > a / 255) ? 0 : (a % 255);
}

// ---------------------------------------------------------------------------
// Prep: quantize x, W0, W1, W2 to fp16 with masks folded in.
// ---------------------------------------------------------------------------
__global__ void __launch_bounds__(256) prep_kernel(
    const float* __restrict__ x,  const float* __restrict__ W0,
    const float* __restrict__ W1, const float* __restrict__ W2)
{
    int t = blockIdx.x * 256 + threadIdx.x;
    const float* src; half* dst;
    int mode, ksh, base;
    if (t < 65536)       { src = x;  dst = g_xq;  mode = -1; ksh = 8; base = t * 4; }
    else if (t < 98304)  { src = W0; dst = g_w0q; mode = 0;  ksh = 8; base = (t - 65536) * 4; }
    else if (t < 163840) { src = W1; dst = g_w1q; mode = 1;  ksh = 9; base = (t - 98304) * 4; }
    else                 { src = W2; dst = g_w2q; mode = 1;  ksh = 9; base = (t - 163840) * 4; }

    float4 v4 = *(const float4*)(src + base);
    float vv[4] = {v4.x, v4.y, v4.z, v4.w};
    int n = base >> ksh;
    int k0 = base & ((1 << ksh) - 1);
    int nd = n % 255;
    half h[4];
    #pragma unroll
    for (int q = 0; q < 4; q++) {
        float v = vv[q];
        int k = k0 + q;
        if (mode == 0 && !(nd >= k)) v = 0.0f;
        if (mode == 1 && !(nd >= (k % 255))) v = 0.0f;
        h[q] = __float2half(v);
    }
    *(uint2*)(dst + base) = *(uint2*)h;
}

// Wout quantize with output mask (MODE 2) -> fp16
__global__ void __launch_bounds__(256) split_wout_kernel(const float* __restrict__ W)
{
    int idx = blockIdx.x * 256 + threadIdx.x;
    int base = idx * 4;
    int n = base >> 9, k0 = base & 511;
    int od = (n >> 5) - 1;
    float4 w4 = *(const float4*)(W + base);
    float wv[4] = {w4.x, w4.y, w4.z, w4.w};
    half h[4];
    #pragma unroll
    for (int q = 0; q < 4; q++) {
        float v = (od >= ((k0 + q) % 255)) ? wv[q] : 0.0f;
        h[q] = __float2half(v);
    }
    *(uint2*)(g_wq + base) = *(uint2*)h;
}

// ---------------------------------------------------------------------------
// Small-layer fp16 HMMA kernel (champion, unchanged).
// ---------------------------------------------------------------------------
template<int K, int MODE>
__global__ void __launch_bounds__(128) layer_kernel(
    const half* __restrict__ Aq, const half* __restrict__ Wq,
    const float* __restrict__ bias, half* __restrict__ Cq)
{
    constexpr int NC = K / 32;
    constexpr int S = 3;
    constexpr uint32_t STG = 6144;
    extern __shared__ half smL[];
    const int tid = threadIdx.x, lane = tid & 31, wn = tid >> 5;
    const int bm = blockIdx.y * 32;
    const int bn = ((int)gridDim.x - 1 - (int)blockIdx.x) * 64;
    const uint32_t sb = smem_u32(smL);

    const int md = (bn / 255 == (bn + 63) / 255) ? ((bn + 63) % 255) : 254;

    int act[NC]; int na = 0;
    #pragma unroll
    for (int kc = 0; kc < NC; kc++) {
        int mm = (MODE == 0) ? (32 * kc) : minmod255(32 * kc);
        if (md >= mm) act[na++] = kc;
    }

    auto load_stage = [&](int s, int kc) {
        uint32_t stg = sb + (uint32_t)s * STG;
        {
            int r = tid >> 2, c = tid & 3;
            uint32_t dsw = (uint32_t)(r * 64 + ((c ^ ((r >> 1) & 3)) << 4));
            cp16(stg + dsw, Aq + (size_t)(bm + r) * K + kc * 32 + c * 8);
        }
        #pragma unroll
        for (int i = 0; i < 2; i++) {
            int idx = tid + i * 128;
            int r = idx >> 2, c = idx & 3;
            uint32_t dsw = (uint32_t)(r * 64 + ((c ^ ((r >> 1) & 3)) << 4));
            cp16(stg + 2048u + dsw, Wq + (size_t)(bn + r) * K + kc * 32 + c * 8);
        }
    };

    int raby[2], swa[2];
    #pragma unroll
    for (int mi = 0; mi < 2; mi++) {
        int r = mi * 16 + (lane & 15);
        raby[mi] = r * 64;
        swa[mi] = (r >> 1) & 3;
    }
    const int hiA = lane >> 4;
    const int nloc = wn * 16 + (((lane >> 3) >> 1) << 3) + (lane & 7);
    const int rbby = nloc * 64, swb = (nloc >> 1) & 3, cbB = (lane >> 3) & 1;

    float acc[2][2][4];
    #pragma unroll
    for (int a = 0; a < 2; a++)
        #pragma unroll
        for (int bq = 0; bq < 2; bq++)
            #pragma unroll
            for (int q = 0; q < 4; q++) acc[a][bq][q] = 0.0f;

    #pragma unroll
    for (int s = 0; s < S - 1; s++) { if (s < na) load_stage(s, act[s]); cp_commit(); }

    #pragma unroll 1
    for (int ii = 0; ii < na; ii++) {
        cp_wait<S - 2>();
        __syncthreads();
        int ld = ii + S - 1;
        if (ld < na) load_stage(ld % S, act[ld]);
        cp_commit();

        uint32_t stg = sb + (uint32_t)(ii % S) * STG;
        #pragma unroll
        for (int k16 = 0; k16 < 2; k16++) {
            uint32_t a0[2][4];
            #pragma unroll
            for (int mi = 0; mi < 2; mi++) {
                uint32_t off = (uint32_t)(raby[mi] + ((((k16 << 1) | hiA) ^ swa[mi]) << 4));
                ldm_x4(a0[mi], stg + off);
            }
            uint32_t boff = (uint32_t)(rbby + ((((k16 << 1) | cbB) ^ swb) << 4));
            uint32_t bh[4];
            ldm_x4(bh, stg + 2048u + boff);
            #pragma unroll
            for (int mi = 0; mi < 2; mi++) {
                mma_f16(acc[mi][0], a0[mi], &bh[0]);
                mma_f16(acc[mi][1], a0[mi], &bh[2]);
            }
        }
    }
    cp_wait<0>();

    const int r0 = bm + (lane >> 2);
    const int c0 = bn + wn * 16 + (lane & 3) * 2;
    #pragma unroll
    for (int mi = 0; mi < 2; mi++) {
        #pragma unroll
        for (int nj = 0; nj < 2; nj++) {
            int c = c0 + nj * 8;
            float b0 = bias[c], b1 = bias[c + 1];
            float v00 = fmaxf(acc[mi][nj][0] + b0, 0.0f);
            float v01 = fmaxf(acc[mi][nj][1] + b1, 0.0f);
            float v10 = fmaxf(acc[mi][nj][2] + b0, 0.0f);
            float v11 = fmaxf(acc[mi][nj][3] + b1, 0.0f);
            *(half2*)(Cq + (size_t)(r0 + mi * 16) * HID + c)     = __floats2half2_rn(v00, v01);
            *(half2*)(Cq + (size_t)(r0 + mi * 16 + 8) * HID + c) = __floats2half2_rn(v10, v11);
        }
    }
}

// ---------------------------------------------------------------------------
// Big fp16 HMMA GEMM (champion, unchanged).
// ---------------------------------------------------------------------------
__global__ void __launch_bounds__(256) gemm_f16_kernel(
    const half* __restrict__ Af, const half* __restrict__ Wf,
    const float* __restrict__ bias, float* __restrict__ C)
{
    constexpr int NC = HID / 32;   // 16
    constexpr int S = 3;
    constexpr uint32_t STG = 16384;
    extern __shared__ half smd[];
    const int tid = threadIdx.x, lane = tid & 31, wrp = tid >> 5;
    const int wm = wrp >> 2, wn = wrp & 3;
    const int bm = blockIdx.y * 128;
    const int bn = ((int)gridDim.x - 1 - (int)blockIdx.x) * 128;
    const uint32_t sb = smem_u32(smd);

    const int T = (bn >> 5) + 2;
    int act[NC]; int na = 0;
    #pragma unroll
    for (int kc = 0; kc < NC; kc++)
        if (minmod255(32 * kc) <= T) act[na++] = kc;

    auto load_stage = [&](int s, int kc) {
        uint32_t stg = sb + (uint32_t)s * STG;
        #pragma unroll
        for (int i = 0; i < 2; i++) {
            int idx = tid + i * 256;
            int r = idx >> 2, c = idx & 3;
            uint32_t dsw = (uint32_t)(r * 64 + ((c ^ ((r >> 1) & 3)) << 4));
            cp16(stg + dsw,         Af + (size_t)(bm + r) * HID + kc * 32 + c * 8);
            cp16(stg + 8192u + dsw, Wf + (size_t)(bn + r) * HID + kc * 32 + c * 8);
        }
    };

    int raby[4], swa[4];
    #pragma unroll
    for (int mi = 0; mi < 4; mi++) {
        int r = wm * 64 + mi * 16 + (lane & 15);
        raby[mi] = r * 64;
        swa[mi] = (r >> 1) & 3;
    }
    const int hiA = lane >> 4;
    int rbby[2], swb[2];
    #pragma unroll
    for (int p = 0; p < 2; p++) {
        int n = wn * 32 + p * 16 + (((lane >> 3) >> 1) << 3) + (lane & 7);
        rbby[p] = n * 64;
        swb[p] = (n >> 1) & 3;
    }
    const int cbB = (lane >> 3) & 1;

    float acc[4][4][4];
    #pragma unroll
    for (int a = 0; a < 4; a++)
        #pragma unroll
        for (int bq = 0; bq < 4; bq++)
            #pragma unroll
            for (int q = 0; q < 4; q++) acc[a][bq][q] = 0.0f;

    #pragma unroll
    for (int s = 0; s < S - 1; s++) { if (s < na) load_stage(s, act[s]); cp_commit(); }

    #pragma unroll 1
    for (int ii = 0; ii < na; ii++) {
        cp_wait<S - 2>();
        __syncthreads();
        int ld = ii + S - 1;
        if (ld < na) load_stage(ld % S, act[ld]);
        cp_commit();

        uint32_t stg = sb + (uint32_t)(ii % S) * STG;
        #pragma unroll
        for (int k16 = 0; k16 < 2; k16++) {
            uint32_t a[4][4];
            #pragma unroll
            for (int mi = 0; mi < 4; mi++) {
                uint32_t off = (uint32_t)(raby[mi] + ((((k16 << 1) | hiA) ^ swa[mi]) << 4));
                ldm_x4(a[mi], stg + off);
            }
            #pragma unroll
            for (int p = 0; p < 2; p++) {
                uint32_t boff = (uint32_t)(rbby[p] + ((((k16 << 1) | cbB) ^ swb[p]) << 4));
                uint32_t wh[4];
                ldm_x4(wh, stg + 8192u + boff);
                #pragma unroll
                for (int mi = 0; mi < 4; mi++) {
                    mma_f16(acc[mi][p * 2 + 0], a[mi], &wh[0]);
                    mma_f16(acc[mi][p * 2 + 1], a[mi], &wh[2]);
                }
            }
        }
    }
    cp_wait<0>();

    const int r0 = bm + wm * 64 + (lane >> 2);
    const int cbase = bn + wn * 32 + (lane & 3) * 2;
    #pragma unroll
    for (int mi = 0; mi < 4; mi++) {
        #pragma unroll
        for (int nj = 0; nj < 4; nj++) {
            int col = cbase + nj * 8;
            float b0 = bias[col], b1 = bias[col + 1];
            float2 v0 = {acc[mi][nj][0] + b0, acc[mi][nj][1] + b1};
            float2 v1 = {acc[mi][nj][2] + b0, acc[mi][nj][3] + b1};
            *(float2*)(C + (size_t)(r0 + mi * 16) * NOUT + col)     = v0;
            *(float2*)(C + (size_t)(r0 + mi * 16 + 8) * NOUT + col) = v1;
        }
    }
}

// ---------------------------------------------------------------------------
// Fused log_px + forward chain. 16 lanes/batch, 2 batches/warp.
// 4-deep register prefetch ring (R16 win) + max-free offset LSE (validated
// bit-identical rel_err in R15): offset = own previous carry, removing the
// two max-shuffles (~60 cyc) from the serial chain.
// ---------------------------------------------------------------------------
__global__ void __launch_bounds__(128) chain_kernel(
    const float* __restrict__ x, const float* __restrict__ theta,
    const float* __restrict__ ulpa, float* __restrict__ out)
{
    __shared__ float s_lpa[255 * 4];
    for (int d = threadIdx.x; d < 255; d += 128) {
        float u0 = ulpa[d * 4 + 0], u1 = ulpa[d * 4 + 1];
        float u2 = ulpa[d * 4 + 2], u3 = ulpa[d * 4 + 3];
        float m = fmaxf(fmaxf(u0, u1), fmaxf(u2, u3));
        float s = expf(u0 - m) + expf(u1 - m) + expf(u2 - m) + expf(u3 - m);
        float lse = m + logf(s);
        s_lpa[d * 4 + 0] = u0 - lse;
        s_lpa[d * 4 + 1] = u1 - lse;
        s_lpa[d * 4 + 2] = u2 - lse;
        s_lpa[d * 4 + 3] = u3 - lse;
    }
    __syncthreads();

    const int lane = threadIdx.x & 31;
    const int wid  = threadIdx.x >> 5;
    const int half_ = lane >> 4;
    const int l    = lane & 15;
    const int i    = l >> 2, j = l & 3;
    const int b    = (blockIdx.x * 4 + wid) * 2 + half_;

    const unsigned FULL = 0xffffffffu;
    const float NL = -0.91893853320467274178f;

    const float* th = theta + (size_t)b * NOUT;
    const float* xb = x + (size_t)b * DIN;

    float carry;
    {   // d = 0
        float mu = __ldg(th + l), ls = __ldg(th + 16 + l);
        float xd = __ldg(xb);
        float sd = __expf(ls) + 0.01f;
        float z = __fdividef(xd - mu, sd);
        float lp = fmaf(-0.5f * z, z, NL) - __logf(sd);
        float v = lp + s_lpa[j];
        carry = __shfl_sync(FULL, v, half_ * 16 + j);
    }

    float mu0 = __ldg(th + 1 * 32 + l), ls0 = __ldg(th + 1 * 32 + 16 + l), xd0 = __ldg(xb + 1);
    float mu1 = __ldg(th + 2 * 32 + l), ls1 = __ldg(th + 2 * 32 + 16 + l), xd1 = __ldg(xb + 2);
    float mu2 = __ldg(th + 3 * 32 + l), ls2 = __ldg(th + 3 * 32 + 16 + l), xd2 = __ldg(xb + 3);
    float mu3 = __ldg(th + 4 * 32 + l), ls3 = __ldg(th + 4 * 32 + 16 + l), xd3 = __ldg(xb + 4);

#define CSTEP(DD, MU, LS, XD) do {                                          \
    int nd_ = (DD) + 4;                                                     \
    float pmu_ = 0.0f, pls_ = 0.0f, pxd_ = 0.0f;                            \
    if (nd_ < 256) {                                                        \
        pmu_ = __ldg(th + nd_ * 32 + l);                                    \
        pls_ = __ldg(th + nd_ * 32 + 16 + l);                               \
        pxd_ = __ldg(xb + nd_);                                             \
    }                                                                       \
    float sd_ = __expf(LS) + 0.01f;                                         \
    float z_ = __fdividef(XD - MU, sd_);                                    \
    float lp_ = fmaf(-0.5f * z_, z_, NL) - __logf(sd_);                     \
    float bt_ = lp_ + s_lpa[(DD) * 4 + j];                                  \
    float ci_ = __shfl_sync(FULL, carry, half_ * 16 + i);                   \
    float e_ = __expf(ci_ + bt_ - carry);                                   \
    float s_ = e_ + __shfl_xor_sync(FULL, e_, 4);                           \
    s_ += __shfl_xor_sync(FULL, s_, 8);                                     \
    carry += __logf(s_ + 1e-30f);                                           \
    MU = pmu_; LS = pls_; XD = pxd_;                                        \
} while (0)

    #pragma unroll 1
    for (int d = 1; d <= 249; d += 4) {
        CSTEP(d,     mu0, ls0, xd0);
        CSTEP(d + 1, mu1, ls1, xd1);
        CSTEP(d + 2, mu2, ls2, xd2);
        CSTEP(d + 3, mu3, ls3, xd3);
    }
    CSTEP(253, mu0, ls0, xd0);
    CSTEP(254, mu1, ls1, xd1);
#undef CSTEP

    {   // d = 255 (values live in slot 2)
        float sd = __expf(ls2) + 0.01f;
        float z = __fdividef(xd2 - mu2, sd);
        float lp = fmaf(-0.5f * z, z, NL) - __logf(sd);
        float ci = __shfl_sync(FULL, carry, half_ * 16 + i);
        float tv = (j == 0) ? (ci + lp) : -1e30f;
        float m = fmaxf(tv, __shfl_xor_sync(FULL, tv, 1));
        m = fmaxf(m, __shfl_xor_sync(FULL, m, 2));
        m = fmaxf(m, __shfl_xor_sync(FULL, m, 4));
        m = fmaxf(m, __shfl_xor_sync(FULL, m, 8));
        float s = __expf(tv - m);
        s += __shfl_xor_sync(FULL, s, 1);
        s += __shfl_xor_sync(FULL, s, 2);
        s += __shfl_xor_sync(FULL, s, 4);
        s += __shfl_xor_sync(FULL, s, 8);
        if (l == 0) out[b] = m + __logf(s);
    }
}

// ---------------------------------------------------------------------------
// kernel_launch (champion schedule; only chain inner step changed)
// ---------------------------------------------------------------------------
extern "C" void kernel_launch(void* const* d_in, const int* in_sizes, int n_in,
                              void* d_out, int out_size)
{
    const float* x    = (const float*)d_in[0];
    const float* W0   = (const float*)d_in[1];
    const float* b0   = (const float*)d_in[2];
    const float* W1   = (const float*)d_in[3];
    const float* b1   = (const float*)d_in[4];
    const float* W2   = (const float*)d_in[5];
    const float* b2   = (const float*)d_in[6];
    const float* Wout = (const float*)d_in[7];
    const float* bout = (const float*)d_in[8];
    const float* ulpa = (const float*)d_in[9];

    float* out   = (float*)d_out;
    float* theta = out + BATCH;

    half *xq, *w0q, *w1q, *w2q, *h0q, *h1q, *h2q, *wq;
    cudaGetSymbolAddress((void**)&xq, g_xq);
    cudaGetSymbolAddress((void**)&w0q, g_w0q);
    cudaGetSymbolAddress((void**)&w1q, g_w1q);
    cudaGetSymbolAddress((void**)&w2q, g_w2q);
    cudaGetSymbolAddress((void**)&h0q, g_h0q);
    cudaGetSymbolAddress((void**)&h1q, g_h1q);
    cudaGetSymbolAddress((void**)&h2q, g_h2q);
    cudaGetSymbolAddress((void**)&wq, g_wq);

    cudaFuncSetAttribute(gemm_f16_kernel,
                         cudaFuncAttributeMaxDynamicSharedMemorySize, 49152);
    cudaFuncSetAttribute(layer_kernel<DIN, 0>,
                         cudaFuncAttributeMaxDynamicSharedMemorySize, 18432);
    cudaFuncSetAttribute(layer_kernel<HID, 1>,
                         cudaFuncAttributeMaxDynamicSharedMemorySize, 18432);

    split_wout_kernel<<<NOUT * HID / 4 / 256, 256>>>(Wout);
    prep_kernel<<<896, 256>>>(x, W0, W1, W2);

    layer_kernel<DIN, 0><<<dim3(HID / 64, BATCH / 32), 128, 18432>>>(
        xq, w0q, b0, h0q);
    layer_kernel<HID, 1><<<dim3(HID / 64, BATCH / 32), 128, 18432>>>(
        h0q, w1q, b1, h1q);
    layer_kernel<HID, 1><<<dim3(HID / 64, BATCH / 32), 128, 18432>>>(
        h1q, w2q, b2, h2q);

    gemm_f16_kernel<<<dim3(NOUT / 128, BATCH / 128), 256, 49152>>>(
        h2q, wq, bout, theta);

    chain_kernel<<<BATCH / 8, 128>>>(x, theta, ulpa, out);
}